// round 15
// baseline (speedup 1.0000x reference)
#include <cuda_runtime.h>
#include <cuda_fp16.h>
#include <mma.h>
#include <math.h>
#include <stdint.h>

using namespace nvcuda;

#define NN      2048
#define GG      32
#define NPG     64
#define EE      16384
#define EPG     512
#define HID     256
#define NH      8
#define HD      32
#define EF      16
#define SCALE_F 0.17677669529663687f   // 1/sqrt(32)

// ---------------- scratch (device globals, no runtime allocation) ----------
__device__ __align__(32) __half g_attn16[NN * HID];

// ======================= cp.async helpers ==================================
__device__ __forceinline__ uint32_t smem_u32(const void* p) {
    uint32_t a;
    asm("{ .reg .u64 t; cvta.to.shared.u64 t, %1; cvt.u32.u64 %0, t; }" : "=r"(a) : "l"(p));
    return a;
}
__device__ __forceinline__ void cp_async16(void* sp, const void* gp) {
    asm volatile("cp.async.cg.shared.global [%0], [%1], 16;"
                 :: "r"(smem_u32(sp)), "l"(gp));
}
#define CP_COMMIT() asm volatile("cp.async.commit_group;" ::: "memory")
#define CP_WAIT0()  asm volatile("cp.async.wait_group 0;" ::: "memory")

// ---------------------------------------------------------------------------
// K1: FUSED per-(graph, head) QKV projection (HMMA) + attention (SIMT).
// 256 blocks, 256 threads, 2 blocks/SM. Weight slices converted fp32->fp16
// + transposed in-kernel (no separate cvt pass).
// smem map (bytes):
//   As  half [64][264]   @ 0        33792   (node tile, converted in-kernel)
//   Bs  half [96][264]   @ 33792    50688   ([n][k]: rows 0-31 Wq, 32-63 Wk, 64-95 Wv)
//   qs  float[64][36]    @ 84480    9216
//   kT  float[32][68]    @ 93696    8704
//   vs  float[64][36]    @ 102400   9216
//   eb  float[512]       @ 111616   2048    -> total 113664
//   sc  float[64][68] overlays Bs after the QKV MMAs.
// ---------------------------------------------------------------------------
static constexpr int K2_OFF_B  = 33792;
static constexpr int K2_OFF_Q  = 84480;
static constexpr int K2_OFF_KT = 93696;
static constexpr int K2_OFF_V  = 102400;
static constexpr int K2_OFF_EB = 111616;
static constexpr int K2_SMEM   = 113664;

__global__ void __launch_bounds__(256, 2) fused_qkv_attn_kernel(
    const float* __restrict__ nodes,
    const int* __restrict__ senders,
    const int* __restrict__ receivers,
    const float* __restrict__ edges,
    const float* __restrict__ We,     // [16,8]
    const float* __restrict__ be,     // [8]
    const float* __restrict__ Wq, const float* __restrict__ bq,
    const float* __restrict__ Wk, const float* __restrict__ bk,
    const float* __restrict__ Wv, const float* __restrict__ bv)
{
    const int g = blockIdx.x >> 3;
    const int h = blockIdx.x & 7;
    const int tid  = threadIdx.x;   // 0..255
    const int wid  = tid >> 5;
    const int lane = tid & 31;

    extern __shared__ __align__(32) char smem[];
    __half* As = (__half*)smem;                       // [64][264]
    __half* Bs = (__half*)(smem + K2_OFF_B);          // [96][264]
    float*  qs = (float*)(smem + K2_OFF_Q);           // [64][36]
    float*  kT = (float*)(smem + K2_OFF_KT);          // [32][68]
    float*  vs = (float*)(smem + K2_OFF_V);           // [64][36]
    float*  eb = (float*)(smem + K2_OFF_EB);          // [512]
    float*  sc = (float*)(smem + K2_OFF_B);           // [64][68] overlay

    // ---- A: direct fp32 load + convert (L2-hot; shared by 8 head-blocks) ----
    {
        const float4* Af = (const float4*)(nodes + g * 64 * 256);
#pragma unroll
        for (int t = 0; t < 16; t++) {                // 4096 float4s
            const int idx = tid + t * 256;
            const int r = idx >> 6, c4 = (idx & 63) * 4;
            float4 v = Af[idx];
            *(__half2*)&As[r * 264 + c4]     = __floats2half2_rn(v.x, v.y);
            *(__half2*)&As[r * 264 + c4 + 2] = __floats2half2_rn(v.z, v.w);
        }
    }
    // ---- B: fp32 weight slice, transpose-convert in-kernel ----
    // Bs[m*32 + n][k] = W_m[k][h*32 + n]. float4 along n (coalesced).
    {
#pragma unroll
        for (int t = 0; t < 24; t++) {                // 3 mats x 8 sub-passes
            const float* Wm = (t < 8) ? Wq : (t < 16) ? Wk : Wv;
            const int mrow  = (t >> 3) * 32;          // 0,32,64
            const int local = tid + (t & 7) * 256;    // 0..2047
            const int k  = local >> 3;                // 0..255
            const int f4 = (local & 7) * 4;           // 0..28
            float4 v = *(const float4*)&Wm[k * 256 + h * 32 + f4];
            Bs[(mrow + f4 + 0) * 264 + k] = __float2half(v.x);
            Bs[(mrow + f4 + 1) * 264 + k] = __float2half(v.y);
            Bs[(mrow + f4 + 2) * 264 + k] = __float2half(v.z);
            Bs[(mrow + f4 + 3) * 264 + k] = __float2half(v.w);
        }
    }
    __syncthreads();

    // ---- QKV via HMMA: C(64x96) in 24 16x16 tiles ----
    {
        const int r0    = (wid & 3) * 16;
        const int chalf = wid >> 2;                   // 0 or 1
        wmma::fragment<wmma::accumulator, 16, 16, 16, float> fc[3];
#pragma unroll
        for (int j = 0; j < 3; j++) wmma::fill_fragment(fc[j], 0.0f);

#pragma unroll
        for (int kk = 0; kk < 256; kk += 16) {
            wmma::fragment<wmma::matrix_a, 16, 16, 16, __half, wmma::row_major> fa;
            wmma::load_matrix_sync(fa, &As[r0 * 264 + kk], 264);
#pragma unroll
            for (int j = 0; j < 3; j++) {
                wmma::fragment<wmma::matrix_b, 16, 16, 16, __half, wmma::col_major> fb;
                wmma::load_matrix_sync(fb, &Bs[(chalf * 48 + j * 16) * 264 + kk], 264);
                wmma::mma_sync(fc[j], fa, fb, fc[j]);
            }
        }
#pragma unroll
        for (int j = 0; j < 3; j++) {
            const int c0  = chalf * 48 + j * 16;
            const int mat = c0 >> 5;                  // 0:q 1:k 2:v
            const int off = c0 & 31;
            if (mat == 0)
                wmma::store_matrix_sync(&qs[r0 * 36 + off], fc[j], 36, wmma::mem_row_major);
            else if (mat == 1)
                wmma::store_matrix_sync(&kT[off * 68 + r0], fc[j], 68, wmma::mem_col_major);
            else
                wmma::store_matrix_sync(&vs[r0 * 36 + off], fc[j], 36, wmma::mem_row_major);
        }
    }
    __syncthreads();

    // ---- bias add + edge-bias compute ----
    for (int i = tid; i < 64 * 32; i += 256) {
        const int r = i >> 5, c = i & 31;
        qs[r * 36 + c] += bq[h * 32 + c];
        vs[r * 36 + c] += bv[h * 32 + c];
    }
    for (int i = tid; i < 32 * 64; i += 256) {
        const int d = i >> 6, n = i & 63;
        kT[d * 68 + n] += bk[h * 32 + d];
    }
    for (int e = tid; e < EPG; e += 256) {
        const float* ef = &edges[(g * EPG + e) * EF];
        float s = be[h];
#pragma unroll
        for (int f = 0; f < EF; f++) s = fmaf(ef[f], We[f * NH + h], s);
        eb[e] = s;
    }
    __syncthreads();

    // ---- scores 64x64 (SIMT): 16x16 thread grid, 4x4 tiles ----
    {
        const int i0 = (tid >> 4) * 4;
        const int j0 = (tid & 15) * 4;
        float acc[4][4];
#pragma unroll
        for (int i = 0; i < 4; i++)
#pragma unroll
            for (int j = 0; j < 4; j++) acc[i][j] = 0.f;
        for (int d = 0; d < 32; d++) {
            float a[4], b[4];
#pragma unroll
            for (int i = 0; i < 4; i++) a[i] = qs[(i0 + i) * 36 + d];
#pragma unroll
            for (int j = 0; j < 4; j++) b[j] = kT[d * 68 + j0 + j];
#pragma unroll
            for (int i = 0; i < 4; i++)
#pragma unroll
                for (int j = 0; j < 4; j++)
                    acc[i][j] = fmaf(a[i], b[j], acc[i][j]);
        }
#pragma unroll
        for (int i = 0; i < 4; i++)
#pragma unroll
            for (int j = 0; j < 4; j++)
                sc[(i0 + i) * 68 + j0 + j] = acc[i][j] * SCALE_F;
    }
    __syncthreads();

    // ---- scatter edge bias (unique pairs) ----
    for (int e = tid; e < EPG; e += 256) {
        const int ge = g * EPG + e;
        const int s  = senders[ge]   - g * 64;
        const int r  = receivers[ge] - g * 64;
        sc[r * 68 + s] += eb[e];
    }
    __syncthreads();

    // ---- softmax over 64 keys, one warp per row ----
    for (int i = wid; i < 64; i += 8) {
        float x0 = sc[i * 68 + lane];
        float x1 = sc[i * 68 + lane + 32];
        float m = fmaxf(x0, x1);
#pragma unroll
        for (int o = 16; o > 0; o >>= 1)
            m = fmaxf(m, __shfl_xor_sync(0xffffffffu, m, o));
        float e0 = expf(x0 - m);
        float e1 = expf(x1 - m);
        float s = e0 + e1;
#pragma unroll
        for (int o = 16; o > 0; o >>= 1)
            s += __shfl_xor_sync(0xffffffffu, s, o);
        const float inv = 1.f / s;
        sc[i * 68 + lane]      = e0 * inv;
        sc[i * 68 + lane + 32] = e1 * inv;
    }
    __syncthreads();

    // ---- AV (SIMT): 64x32, thread tile 2 rows x 4 cols -> fp16 global ----
    {
        const int i0 = (tid >> 3) * 2;
        const int d0 = (tid & 7) * 4;
        float acc[2][4];
#pragma unroll
        for (int i = 0; i < 2; i++)
#pragma unroll
            for (int d = 0; d < 4; d++) acc[i][d] = 0.f;
        for (int j = 0; j < 64; j++) {
            const float p0 = sc[i0 * 68 + j];
            const float p1 = sc[(i0 + 1) * 68 + j];
            float b[4];
#pragma unroll
            for (int d = 0; d < 4; d++) b[d] = vs[j * 36 + d0 + d];
#pragma unroll
            for (int d = 0; d < 4; d++) {
                acc[0][d] = fmaf(p0, b[d], acc[0][d]);
                acc[1][d] = fmaf(p1, b[d], acc[1][d]);
            }
        }
#pragma unroll
        for (int i = 0; i < 2; i++) {
            const int idx = (g * 64 + i0 + i) * 256 + h * 32 + d0;
            *(__half2*)&g_attn16[idx]     = __floats2half2_rn(acc[i][0], acc[i][1]);
            *(__half2*)&g_attn16[idx + 2] = __floats2half2_rn(acc[i][2], acc[i][3]);
        }
    }
}

// ---------------------------------------------------------------------------
// K2: out projection. 32x64 tiles, 256 blocks. A via cp.async, Wo slice
// transpose-converted in-kernel from fp32.
// smem: As half[32][264] (16896) + Bs half[64][264] (33792) = 50688 (dynamic).
// ---------------------------------------------------------------------------
static constexpr int K3_OFF_B = 16896;
static constexpr int K3_SMEM  = 50688;

__global__ void __launch_bounds__(256) out_hmma_kernel(
    const float* __restrict__ Wo, const float* __restrict__ bo,
    float* __restrict__ outp)
{
    const int m0 = blockIdx.x * 32;       // 0..2016
    const int n0 = blockIdx.y * 64;       // 0..192
    const int tid = threadIdx.x;
    const int wid = tid >> 5;

    extern __shared__ __align__(32) char smem[];
    __half* As = (__half*)smem;                   // [32][264]
    __half* Bs = (__half*)(smem + K3_OFF_B);      // [64][264]  ([n][k])

    // ---- A: cp.async fp16 staging ----
    {
        const __half* Ag = g_attn16 + m0 * 256;
#pragma unroll
        for (int t = 0; t < 4; t++) {             // 1024 chunks
            const int idx = tid + t * 256;
            const int r = idx >> 5, q8 = (idx & 31) * 8;
            cp_async16(&As[r * 264 + q8], Ag + r * 256 + q8);
        }
        CP_COMMIT();
    }
    // ---- B: Wo fp32 slice, transpose-convert in-kernel ----
    // Bs[n][k] = Wo[k][n0 + n]; float4 along n (coalesced).
    {
#pragma unroll
        for (int t = 0; t < 16; t++) {            // 4096 float4s
            const int idx = tid + t * 256;
            const int k  = idx >> 4;              // 0..255
            const int f4 = (idx & 15) * 4;        // 0..60
            float4 v = *(const float4*)&Wo[k * 256 + n0 + f4];
            Bs[(f4 + 0) * 264 + k] = __float2half(v.x);
            Bs[(f4 + 1) * 264 + k] = __float2half(v.y);
            Bs[(f4 + 2) * 264 + k] = __float2half(v.z);
            Bs[(f4 + 3) * 264 + k] = __float2half(v.w);
        }
    }
    CP_WAIT0();
    __syncthreads();

    // 8 warps, one 16x16 tile each: r0 = (w&1)*16, c0 = (w>>1)*16
    const int r0 = (wid & 1) * 16;
    const int c0 = (wid >> 1) * 16;
    wmma::fragment<wmma::accumulator, 16, 16, 16, float> fc;
    wmma::fill_fragment(fc, 0.0f);
#pragma unroll
    for (int kk = 0; kk < 256; kk += 16) {
        wmma::fragment<wmma::matrix_a, 16, 16, 16, __half, wmma::row_major> fa;
        wmma::fragment<wmma::matrix_b, 16, 16, 16, __half, wmma::col_major> fb;
        wmma::load_matrix_sync(fa, &As[r0 * 264 + kk], 264);
        wmma::load_matrix_sync(fb, &Bs[c0 * 264 + kk], 264);
        wmma::mma_sync(fc, fa, fb, fc);
    }
    __syncthreads();   // As dead; overlay epilogue buffer

    float* Cs = (float*)smem;                     // [32][68] = 8704 B
    wmma::store_matrix_sync(&Cs[r0 * 68 + c0], fc, 68, wmma::mem_row_major);
    __syncthreads();

#pragma unroll
    for (int i = tid; i < 512; i += 256) {        // 32 rows x 16 float4
        const int r = i >> 4, c4 = (i & 15) * 4;
        float4 v = *(float4*)&Cs[r * 68 + c4];
        v.x += bo[n0 + c4 + 0];
        v.y += bo[n0 + c4 + 1];
        v.z += bo[n0 + c4 + 2];
        v.w += bo[n0 + c4 + 3];
        *(float4*)&outp[(m0 + r) * 256 + n0 + c4] = v;
    }
}

// ---------------------------------------------------------------------------
extern "C" void kernel_launch(void* const* d_in, const int* in_sizes, int n_in,
                              void* d_out, int out_size)
{
    const float* nodes     = (const float*)d_in[0];
    const float* edges     = (const float*)d_in[1];
    const int*   senders   = (const int*)d_in[3];
    const int*   receivers = (const int*)d_in[4];
    const float* Wq = (const float*)d_in[5];
    const float* bq = (const float*)d_in[6];
    const float* Wk = (const float*)d_in[7];
    const float* bk = (const float*)d_in[8];
    const float* Wv = (const float*)d_in[9];
    const float* bv = (const float*)d_in[10];
    const float* Wo = (const float*)d_in[11];
    const float* bo = (const float*)d_in[12];
    const float* We = (const float*)d_in[13];
    const float* be = (const float*)d_in[14];
    float* out = (float*)d_out;

    cudaFuncSetAttribute(fused_qkv_attn_kernel,
                         cudaFuncAttributeMaxDynamicSharedMemorySize, K2_SMEM);
    cudaFuncSetAttribute(out_hmma_kernel,
                         cudaFuncAttributeMaxDynamicSharedMemorySize, K3_SMEM);

    fused_qkv_attn_kernel<<<GG * NH, 256, K2_SMEM>>>(nodes, senders, receivers,
                                                     edges, We, be,
                                                     Wq, bq, Wk, bk, Wv, bv);
    out_hmma_kernel<<<dim3(64, 4), 256, K3_SMEM>>>(Wo, bo, out);
}

// round 16
// speedup vs baseline: 1.1670x; 1.1670x over previous
#include <cuda_runtime.h>
#include <cuda_fp16.h>
#include <mma.h>
#include <math.h>
#include <stdint.h>

using namespace nvcuda;

#define NN      2048
#define GG      32
#define NPG     64
#define EE      16384
#define EPG     512
#define HID     256
#define NH      8
#define HD      32
#define EF      16
#define SCALE_F 0.17677669529663687f   // 1/sqrt(32)

// ---------------- scratch (device globals, no runtime allocation) ----------
__device__ __align__(32) __half g_wT16[1024 * HID];   // rows 0-767: Wq|Wk|Wv cols, 768-1023: Wo cols (K contiguous)
__device__ __align__(32) __half g_attn16[NN * HID];

// ======================= cp.async helpers ==================================
__device__ __forceinline__ uint32_t smem_u32(const void* p) {
    uint32_t a;
    asm("{ .reg .u64 t; cvta.to.shared.u64 t, %1; cvt.u32.u64 %0, t; }" : "=r"(a) : "l"(p));
    return a;
}
__device__ __forceinline__ void cp_async16(void* sp, const void* gp) {
    asm volatile("cp.async.cg.shared.global [%0], [%1], 16;"
                 :: "r"(smem_u32(sp)), "l"(gp));
}
#define CP_COMMIT() asm volatile("cp.async.commit_group;" ::: "memory")
#define CP_WAIT0()  asm volatile("cp.async.wait_group 0;" ::: "memory")

// ---------------------------------------------------------------------------
// K1: weight transpose-convert (one thread = one element; minimal serial depth).
// 256 blocks x 1024 threads: each block transposes a 32x32 tile of one weight
// matrix into g_wT16 (n-major, K contiguous).
// ---------------------------------------------------------------------------
__global__ void __launch_bounds__(1024) cvt_kernel(
    const float* __restrict__ Wq, const float* __restrict__ Wk,
    const float* __restrict__ Wv, const float* __restrict__ Wo)
{
    const int bx = blockIdx.x;
    const int tx = threadIdx.x;   // 0..31  (column within tile)
    const int ty = threadIdx.y;   // 0..31  (row within tile)
    const int n0 = (bx & 31) * 32;
    const int k0 = (bx >> 5) * 32;
    __shared__ float s[32][33];
    const int mat  = n0 >> 8;
    const int col0 = n0 & 255;
    const float* W = (mat == 0) ? Wq : (mat == 1) ? Wk : (mat == 2) ? Wv : Wo;
    // load W[k0+ty][col0+tx] (coalesced along tx)
    s[ty][tx] = W[(k0 + ty) * 256 + col0 + tx];
    __syncthreads();
    // store transposed: g_wT16[(n0+ty)*256 + k0+tx] = W[k0+tx][col0+ty]
    g_wT16[(n0 + ty) * 256 + k0 + tx] = __float2half(s[tx][ty]);
}

// ---------------------------------------------------------------------------
// K2: FUSED per-(graph, head) QKV projection (HMMA) + attention (SIMT).
// 256 blocks, 256 threads, 2 blocks/SM (113.7KB smem x2 fits 228KB/SM).
// smem map (bytes):
//   As  half [64][264]   @ 0        33792   (node tile, converted in-kernel)
//   Bs  half [96][264]   @ 33792    50688   (wq|wk|wv head slices; sc overlays)
//   qs  float[64][36]    @ 84480    9216
//   kT  float[32][68]    @ 93696    8704
//   vs  float[64][36]    @ 102400   9216
//   eb  float[512]       @ 111616   2048    -> total 113664
// ---------------------------------------------------------------------------
static constexpr int K2_OFF_B  = 33792;
static constexpr int K2_OFF_Q  = 84480;
static constexpr int K2_OFF_KT = 93696;
static constexpr int K2_OFF_V  = 102400;
static constexpr int K2_OFF_EB = 111616;
static constexpr int K2_SMEM   = 113664;

__global__ void __launch_bounds__(256, 2) fused_qkv_attn_kernel(
    const float* __restrict__ nodes,
    const int* __restrict__ senders,
    const int* __restrict__ receivers,
    const float* __restrict__ edges,
    const float* __restrict__ We,     // [16,8]
    const float* __restrict__ be,     // [8]
    const float* __restrict__ bq, const float* __restrict__ bk,
    const float* __restrict__ bv)
{
    const int g = blockIdx.x >> 3;
    const int h = blockIdx.x & 7;
    const int tid  = threadIdx.x;   // 0..255
    const int wid  = tid >> 5;
    const int lane = tid & 31;

    extern __shared__ __align__(32) char smem[];
    __half* As = (__half*)smem;                       // [64][264]
    __half* Bs = (__half*)(smem + K2_OFF_B);          // [96][264]
    float*  qs = (float*)(smem + K2_OFF_Q);           // [64][36]
    float*  kT = (float*)(smem + K2_OFF_KT);          // [32][68]
    float*  vs = (float*)(smem + K2_OFF_V);           // [64][36]
    float*  eb = (float*)(smem + K2_OFF_EB);          // [512]
    float*  sc = (float*)(smem + K2_OFF_B);           // [64][68] overlay

    // ---- B: cp.async burst first (overlaps with A convert below) ----
    {
#pragma unroll
        for (int t = 0; t < 12; t++) {                // 3072 16B chunks
            const int idx = tid + t * 256;
            const int r = idx >> 5, q8 = (idx & 31) * 8;
            const int mat = r >> 5, rr = r & 31;
            cp_async16(&Bs[r * 264 + q8],
                       g_wT16 + (mat * 256 + h * 32 + rr) * 256 + q8);
        }
        CP_COMMIT();
    }
    // ---- A: direct fp32 load + convert (L2-hot; shared by 8 head-blocks) ----
    {
        const float4* Af = (const float4*)(nodes + g * 64 * 256);
#pragma unroll
        for (int t = 0; t < 16; t++) {                // 4096 float4s
            const int idx = tid + t * 256;
            const int r = idx >> 6, c4 = (idx & 63) * 4;
            float4 v = Af[idx];
            *(__half2*)&As[r * 264 + c4]     = __floats2half2_rn(v.x, v.y);
            *(__half2*)&As[r * 264 + c4 + 2] = __floats2half2_rn(v.z, v.w);
        }
    }
    CP_WAIT0();
    __syncthreads();

    // ---- QKV via HMMA: C(64x96) in 24 16x16 tiles ----
    {
        const int r0    = (wid & 3) * 16;
        const int chalf = wid >> 2;                   // 0 or 1
        wmma::fragment<wmma::accumulator, 16, 16, 16, float> fc[3];
#pragma unroll
        for (int j = 0; j < 3; j++) wmma::fill_fragment(fc[j], 0.0f);

#pragma unroll
        for (int kk = 0; kk < 256; kk += 16) {
            wmma::fragment<wmma::matrix_a, 16, 16, 16, __half, wmma::row_major> fa;
            wmma::load_matrix_sync(fa, &As[r0 * 264 + kk], 264);
#pragma unroll
            for (int j = 0; j < 3; j++) {
                wmma::fragment<wmma::matrix_b, 16, 16, 16, __half, wmma::col_major> fb;
                wmma::load_matrix_sync(fb, &Bs[(chalf * 48 + j * 16) * 264 + kk], 264);
                wmma::mma_sync(fc[j], fa, fb, fc[j]);
            }
        }
#pragma unroll
        for (int j = 0; j < 3; j++) {
            const int c0  = chalf * 48 + j * 16;
            const int mat = c0 >> 5;                  // 0:q 1:k 2:v
            const int off = c0 & 31;
            if (mat == 0)
                wmma::store_matrix_sync(&qs[r0 * 36 + off], fc[j], 36, wmma::mem_row_major);
            else if (mat == 1)
                wmma::store_matrix_sync(&kT[off * 68 + r0], fc[j], 68, wmma::mem_col_major);
            else
                wmma::store_matrix_sync(&vs[r0 * 36 + off], fc[j], 36, wmma::mem_row_major);
        }
    }
    __syncthreads();

    // ---- bias add + edge-bias compute ----
    for (int i = tid; i < 64 * 32; i += 256) {
        const int r = i >> 5, c = i & 31;
        qs[r * 36 + c] += bq[h * 32 + c];
        vs[r * 36 + c] += bv[h * 32 + c];
    }
    for (int i = tid; i < 32 * 64; i += 256) {
        const int d = i >> 6, n = i & 63;
        kT[d * 68 + n] += bk[h * 32 + d];
    }
    for (int e = tid; e < EPG; e += 256) {
        const float* ef = &edges[(g * EPG + e) * EF];
        float s = be[h];
#pragma unroll
        for (int f = 0; f < EF; f++) s = fmaf(ef[f], We[f * NH + h], s);
        eb[e] = s;
    }
    __syncthreads();

    // ---- scores 64x64 (SIMT): 16x16 thread grid, 4x4 tiles ----
    {
        const int i0 = (tid >> 4) * 4;
        const int j0 = (tid & 15) * 4;
        float acc[4][4];
#pragma unroll
        for (int i = 0; i < 4; i++)
#pragma unroll
            for (int j = 0; j < 4; j++) acc[i][j] = 0.f;
        for (int d = 0; d < 32; d++) {
            float a[4], b[4];
#pragma unroll
            for (int i = 0; i < 4; i++) a[i] = qs[(i0 + i) * 36 + d];
#pragma unroll
            for (int j = 0; j < 4; j++) b[j] = kT[d * 68 + j0 + j];
#pragma unroll
            for (int i = 0; i < 4; i++)
#pragma unroll
                for (int j = 0; j < 4; j++)
                    acc[i][j] = fmaf(a[i], b[j], acc[i][j]);
        }
#pragma unroll
        for (int i = 0; i < 4; i++)
#pragma unroll
            for (int j = 0; j < 4; j++)
                sc[(i0 + i) * 68 + j0 + j] = acc[i][j] * SCALE_F;
    }
    __syncthreads();

    // ---- scatter edge bias (unique pairs) ----
    for (int e = tid; e < EPG; e += 256) {
        const int ge = g * EPG + e;
        const int s  = senders[ge]   - g * 64;
        const int r  = receivers[ge] - g * 64;
        sc[r * 68 + s] += eb[e];
    }
    __syncthreads();

    // ---- softmax over 64 keys, one warp per row ----
    for (int i = wid; i < 64; i += 8) {
        float x0 = sc[i * 68 + lane];
        float x1 = sc[i * 68 + lane + 32];
        float m = fmaxf(x0, x1);
#pragma unroll
        for (int o = 16; o > 0; o >>= 1)
            m = fmaxf(m, __shfl_xor_sync(0xffffffffu, m, o));
        float e0 = expf(x0 - m);
        float e1 = expf(x1 - m);
        float s = e0 + e1;
#pragma unroll
        for (int o = 16; o > 0; o >>= 1)
            s += __shfl_xor_sync(0xffffffffu, s, o);
        const float inv = 1.f / s;
        sc[i * 68 + lane]      = e0 * inv;
        sc[i * 68 + lane + 32] = e1 * inv;
    }
    __syncthreads();

    // ---- AV (SIMT): 64x32, thread tile 2 rows x 4 cols -> fp16 global ----
    {
        const int i0 = (tid >> 3) * 2;
        const int d0 = (tid & 7) * 4;
        float acc[2][4];
#pragma unroll
        for (int i = 0; i < 2; i++)
#pragma unroll
            for (int d = 0; d < 4; d++) acc[i][d] = 0.f;
        for (int j = 0; j < 64; j++) {
            const float p0 = sc[i0 * 68 + j];
            const float p1 = sc[(i0 + 1) * 68 + j];
            float b[4];
#pragma unroll
            for (int d = 0; d < 4; d++) b[d] = vs[j * 36 + d0 + d];
#pragma unroll
            for (int d = 0; d < 4; d++) {
                acc[0][d] = fmaf(p0, b[d], acc[0][d]);
                acc[1][d] = fmaf(p1, b[d], acc[1][d]);
            }
        }
#pragma unroll
        for (int i = 0; i < 2; i++) {
            const int idx = (g * 64 + i0 + i) * 256 + h * 32 + d0;
            *(__half2*)&g_attn16[idx]     = __floats2half2_rn(acc[i][0], acc[i][1]);
            *(__half2*)&g_attn16[idx + 2] = __floats2half2_rn(acc[i][2], acc[i][3]);
        }
    }
}

// ---------------------------------------------------------------------------
// K3: out projection. 32x64 tiles, 256 blocks, full-K single-stage staging.
// smem: As half[32][264] (16896) + Bs half[64][264] (33792) = 50688 (dynamic).
// ---------------------------------------------------------------------------
static constexpr int K3_OFF_B = 16896;
static constexpr int K3_SMEM  = 50688;

__global__ void __launch_bounds__(256) out_hmma_kernel(
    const float* __restrict__ bo, float* __restrict__ outp)
{
    const int m0 = blockIdx.x * 32;       // 0..2016
    const int n0 = blockIdx.y * 64;       // 0..192
    const int tid = threadIdx.x;
    const int wid = tid >> 5;

    extern __shared__ __align__(32) char smem[];
    __half* As = (__half*)smem;                   // [32][264]
    __half* Bs = (__half*)(smem + K3_OFF_B);      // [64][264]

    {
        const __half* Ag = g_attn16 + m0 * 256;
        const __half* Bg = g_wT16 + (768 + n0) * 256;
#pragma unroll
        for (int t = 0; t < 4; t++) {             // 1024 chunks A
            const int idx = tid + t * 256;
            const int r = idx >> 5, q8 = (idx & 31) * 8;
            cp_async16(&As[r * 264 + q8], Ag + r * 256 + q8);
        }
#pragma unroll
        for (int t = 0; t < 8; t++) {             // 2048 chunks B
            const int idx = tid + t * 256;
            const int r = idx >> 5, q8 = (idx & 31) * 8;
            cp_async16(&Bs[r * 264 + q8], Bg + r * 256 + q8);
        }
        CP_COMMIT();
        CP_WAIT0();
    }
    __syncthreads();

    // 8 warps, one 16x16 tile each: r0 = (w&1)*16, c0 = (w>>1)*16
    const int r0 = (wid & 1) * 16;
    const int c0 = (wid >> 1) * 16;
    wmma::fragment<wmma::accumulator, 16, 16, 16, float> fc;
    wmma::fill_fragment(fc, 0.0f);
#pragma unroll
    for (int kk = 0; kk < 256; kk += 16) {
        wmma::fragment<wmma::matrix_a, 16, 16, 16, __half, wmma::row_major> fa;
        wmma::fragment<wmma::matrix_b, 16, 16, 16, __half, wmma::col_major> fb;
        wmma::load_matrix_sync(fa, &As[r0 * 264 + kk], 264);
        wmma::load_matrix_sync(fb, &Bs[c0 * 264 + kk], 264);
        wmma::mma_sync(fc, fa, fb, fc);
    }
    __syncthreads();   // As dead; overlay epilogue buffer

    float* Cs = (float*)smem;                     // [32][68] = 8704 B
    wmma::store_matrix_sync(&Cs[r0 * 68 + c0], fc, 68, wmma::mem_row_major);
    __syncthreads();

#pragma unroll
    for (int i = tid; i < 512; i += 256) {        // 32 rows x 16 float4
        const int r = i >> 4, c4 = (i & 15) * 4;
        float4 v = *(float4*)&Cs[r * 68 + c4];
        v.x += bo[n0 + c4 + 0];
        v.y += bo[n0 + c4 + 1];
        v.z += bo[n0 + c4 + 2];
        v.w += bo[n0 + c4 + 3];
        *(float4*)&outp[(m0 + r) * 256 + n0 + c4] = v;
    }
}

// ---------------------------------------------------------------------------
extern "C" void kernel_launch(void* const* d_in, const int* in_sizes, int n_in,
                              void* d_out, int out_size)
{
    const float* nodes     = (const float*)d_in[0];
    const float* edges     = (const float*)d_in[1];
    const int*   senders   = (const int*)d_in[3];
    const int*   receivers = (const int*)d_in[4];
    const float* Wq = (const float*)d_in[5];
    const float* bq = (const float*)d_in[6];
    const float* Wk = (const float*)d_in[7];
    const float* bk = (const float*)d_in[8];
    const float* Wv = (const float*)d_in[9];
    const float* bv = (const float*)d_in[10];
    const float* Wo = (const float*)d_in[11];
    const float* bo = (const float*)d_in[12];
    const float* We = (const float*)d_in[13];
    const float* be = (const float*)d_in[14];
    float* out = (float*)d_out;

    cudaFuncSetAttribute(fused_qkv_attn_kernel,
                         cudaFuncAttributeMaxDynamicSharedMemorySize, K2_SMEM);
    cudaFuncSetAttribute(out_hmma_kernel,
                         cudaFuncAttributeMaxDynamicSharedMemorySize, K3_SMEM);

    cvt_kernel<<<256, dim3(32, 32)>>>(Wq, Wk, Wv, Wo);
    fused_qkv_attn_kernel<<<GG * NH, 256, K2_SMEM>>>(nodes, senders, receivers,
                                                     edges, We, be, bq, bk, bv);
    out_hmma_kernel<<<dim3(64, 4), 256, K3_SMEM>>>(bo, out);
}

// round 17
// speedup vs baseline: 1.2373x; 1.0602x over previous
#include <cuda_runtime.h>
#include <cuda_fp16.h>
#include <mma.h>
#include <math.h>
#include <stdint.h>

using namespace nvcuda;

#define NN      2048
#define GG      32
#define NPG     64
#define EE      16384
#define EPG     512
#define HID     256
#define NH      8
#define HD      32
#define EF      16
#define SCALE_F 0.17677669529663687f   // 1/sqrt(32)

// ---------------- scratch (device globals, no runtime allocation) ----------
__device__ __align__(32) __half g_wT16[1024 * HID];   // rows 0-767: Wq|Wk|Wv cols, 768-1023: Wo cols (K contiguous)
__device__ __align__(32) __half g_attn16[NN * HID];

// ======================= cp.async helpers ==================================
__device__ __forceinline__ uint32_t smem_u32(const void* p) {
    uint32_t a;
    asm("{ .reg .u64 t; cvta.to.shared.u64 t, %1; cvt.u32.u64 %0, t; }" : "=r"(a) : "l"(p));
    return a;
}
__device__ __forceinline__ void cp_async16(void* sp, const void* gp) {
    asm volatile("cp.async.cg.shared.global [%0], [%1], 16;"
                 :: "r"(smem_u32(sp)), "l"(gp));
}
#define CP_COMMIT() asm volatile("cp.async.commit_group;" ::: "memory")
#define CP_WAIT0()  asm volatile("cp.async.wait_group 0;" ::: "memory")

// ---------------------------------------------------------------------------
// K1: weight transpose-convert (R12 measured-best config: 256 thr, 4/thread).
// ---------------------------------------------------------------------------
__global__ void __launch_bounds__(256) cvt_kernel(
    const float* __restrict__ Wq, const float* __restrict__ Wk,
    const float* __restrict__ Wv, const float* __restrict__ Wo)
{
    const int bx = blockIdx.x;
    const int tx = threadIdx.x;   // 0..31
    const int ty = threadIdx.y;   // 0..7
    const int n0 = (bx & 31) * 32;
    const int k0 = (bx >> 5) * 32;
    __shared__ float s[32][33];
    const int mat  = n0 >> 8;
    const int col0 = n0 & 255;
    const float* W = (mat == 0) ? Wq : (mat == 1) ? Wk : (mat == 2) ? Wv : Wo;
#pragma unroll
    for (int j = 0; j < 4; j++) {
        const int k = k0 + ty + j * 8;
        s[ty + j * 8][tx] = W[k * 256 + col0 + tx];
    }
    __syncthreads();
#pragma unroll
    for (int j = 0; j < 4; j++) {
        const int n = n0 + ty + j * 8;
        g_wT16[n * 256 + k0 + tx] = __float2half(s[tx][ty + j * 8]);
    }
}

// ---------------------------------------------------------------------------
// K2: FUSED per-(graph, head): QKV (HMMA) + scores (HMMA) + softmax (SIMT)
// + AV (HMMA). 256 blocks, 256 threads, 2 blocks/SM.
// smem map (bytes):
//   As  half [64][264]   @ 0        33792   staging; overlaid after QKV MMA by:
//       q16 half[64][40] @ 0     5120  (bias+SCALE folded)
//       k16 half[64][40] @ 5120  5120  (bias folded)
//       v16 half[64][40] @ 10240 5120  (bias folded)
//       p16 half[64][72] @ 15360 9216  (probabilities)
//   Bs  half [96][264]   @ 33792    50688   staging; overlaid by sc f32[64][68]
//   Cf  f32  [64][100]   @ 84480    25600   QKV accum scratch; later AV out [64][36]
//   eb  f32  [512]       @ 110080   2048    -> total 112128
// ---------------------------------------------------------------------------
static constexpr int K2_OFF_B   = 33792;
static constexpr int K2_OFF_Q16 = 0;
static constexpr int K2_OFF_K16 = 5120;
static constexpr int K2_OFF_V16 = 10240;
static constexpr int K2_OFF_P16 = 15360;
static constexpr int K2_OFF_C   = 84480;
static constexpr int K2_OFF_EB  = 110080;
static constexpr int K2_SMEM    = 112128;

__global__ void __launch_bounds__(256, 2) fused_qkv_attn_kernel(
    const float* __restrict__ nodes,
    const int* __restrict__ senders,
    const int* __restrict__ receivers,
    const float* __restrict__ edges,
    const float* __restrict__ We,     // [16,8]
    const float* __restrict__ be,     // [8]
    const float* __restrict__ bq, const float* __restrict__ bk,
    const float* __restrict__ bv)
{
    const int g = blockIdx.x >> 3;
    const int h = blockIdx.x & 7;
    const int tid  = threadIdx.x;   // 0..255
    const int wid  = tid >> 5;
    const int lane = tid & 31;

    extern __shared__ __align__(32) char smem[];
    __half* As  = (__half*)smem;                      // [64][264]
    __half* Bs  = (__half*)(smem + K2_OFF_B);         // [96][264]
    __half* q16 = (__half*)(smem + K2_OFF_Q16);       // [64][40]
    __half* k16 = (__half*)(smem + K2_OFF_K16);       // [64][40]
    __half* v16 = (__half*)(smem + K2_OFF_V16);       // [64][40]
    __half* p16 = (__half*)(smem + K2_OFF_P16);       // [64][72]
    float*  Cf  = (float*)(smem + K2_OFF_C);          // [64][100] / later [64][36]
    float*  eb  = (float*)(smem + K2_OFF_EB);         // [512]
    float*  sc  = (float*)(smem + K2_OFF_B);          // [64][68] overlay

    // ---- B: cp.async burst (overlaps with A convert below) ----
    {
#pragma unroll
        for (int t = 0; t < 12; t++) {                // 3072 16B chunks
            const int idx = tid + t * 256;
            const int r = idx >> 5, q8 = (idx & 31) * 8;
            const int mat = r >> 5, rr = r & 31;
            cp_async16(&Bs[r * 264 + q8],
                       g_wT16 + (mat * 256 + h * 32 + rr) * 256 + q8);
        }
        CP_COMMIT();
    }
    // ---- A: direct fp32 load + convert ----
    {
        const float4* Af = (const float4*)(nodes + g * 64 * 256);
#pragma unroll
        for (int t = 0; t < 16; t++) {                // 4096 float4s
            const int idx = tid + t * 256;
            const int r = idx >> 6, c4 = (idx & 63) * 4;
            float4 v = Af[idx];
            *(__half2*)&As[r * 264 + c4]     = __floats2half2_rn(v.x, v.y);
            *(__half2*)&As[r * 264 + c4 + 2] = __floats2half2_rn(v.z, v.w);
        }
    }
    CP_WAIT0();
    __syncthreads();

    // ---- QKV via HMMA: C(64x96) -> Cf fp32 ----
    {
        const int r0    = (wid & 3) * 16;
        const int chalf = wid >> 2;                   // 0 or 1
        wmma::fragment<wmma::accumulator, 16, 16, 16, float> fc[3];
#pragma unroll
        for (int j = 0; j < 3; j++) wmma::fill_fragment(fc[j], 0.0f);
#pragma unroll
        for (int kk = 0; kk < 256; kk += 16) {
            wmma::fragment<wmma::matrix_a, 16, 16, 16, __half, wmma::row_major> fa;
            wmma::load_matrix_sync(fa, &As[r0 * 264 + kk], 264);
#pragma unroll
            for (int j = 0; j < 3; j++) {
                wmma::fragment<wmma::matrix_b, 16, 16, 16, __half, wmma::col_major> fb;
                wmma::load_matrix_sync(fb, &Bs[(chalf * 48 + j * 16) * 264 + kk], 264);
                wmma::mma_sync(fc[j], fa, fb, fc[j]);
            }
        }
#pragma unroll
        for (int j = 0; j < 3; j++)
            wmma::store_matrix_sync(&Cf[r0 * 100 + chalf * 48 + j * 16], fc[j],
                                    100, wmma::mem_row_major);
    }
    __syncthreads();   // As/Bs dead from here

    // ---- convert QKV fp32 -> fp16 tiles (bias folded; SCALE folded into q) ----
    for (int i = tid; i < 64 * 96; i += 256) {
        const int r = i / 96, c = i % 96;
        const int mat = c >> 5, d = c & 31;
        const float v = Cf[r * 100 + c];
        if (mat == 0)      q16[r * 40 + d] = __float2half((v + bq[h * 32 + d]) * SCALE_F);
        else if (mat == 1) k16[r * 40 + d] = __float2half(v + bk[h * 32 + d]);
        else               v16[r * 40 + d] = __float2half(v + bv[h * 32 + d]);
    }
    // ---- edge bias ----
    for (int e = tid; e < EPG; e += 256) {
        const float* ef = &edges[(g * EPG + e) * EF];
        float s = be[h];
#pragma unroll
        for (int f = 0; f < EF; f++) s = fmaf(ef[f], We[f * NH + h], s);
        eb[e] = s;
    }
    __syncthreads();

    // ---- scores via HMMA: S(64x64) = q16 @ k16^T -> sc fp32 ----
    {
#pragma unroll
        for (int t2 = 0; t2 < 2; t2++) {
            const int t  = wid + t2 * 8;              // 0..15
            const int i0 = (t >> 2) * 16;
            const int j0 = (t & 3) * 16;
            wmma::fragment<wmma::accumulator, 16, 16, 16, float> fs;
            wmma::fill_fragment(fs, 0.0f);
#pragma unroll
            for (int kk = 0; kk < 32; kk += 16) {
                wmma::fragment<wmma::matrix_a, 16, 16, 16, __half, wmma::row_major> fa;
                wmma::fragment<wmma::matrix_b, 16, 16, 16, __half, wmma::col_major> fb;
                wmma::load_matrix_sync(fa, &q16[i0 * 40 + kk], 40);
                wmma::load_matrix_sync(fb, &k16[j0 * 40 + kk], 40);
                wmma::mma_sync(fs, fa, fb, fs);
            }
            wmma::store_matrix_sync(&sc[i0 * 68 + j0], fs, 68, wmma::mem_row_major);
        }
    }
    __syncthreads();

    // ---- scatter edge bias (unique pairs) ----
    for (int e = tid; e < EPG; e += 256) {
        const int ge = g * EPG + e;
        const int s  = senders[ge]   - g * 64;
        const int r  = receivers[ge] - g * 64;
        sc[r * 68 + s] += eb[e];
    }
    __syncthreads();

    // ---- softmax over 64 keys, one warp per row ----
    for (int i = wid; i < 64; i += 8) {
        float x0 = sc[i * 68 + lane];
        float x1 = sc[i * 68 + lane + 32];
        float m = fmaxf(x0, x1);
#pragma unroll
        for (int o = 16; o > 0; o >>= 1)
            m = fmaxf(m, __shfl_xor_sync(0xffffffffu, m, o));
        float e0 = expf(x0 - m);
        float e1 = expf(x1 - m);
        float s = e0 + e1;
#pragma unroll
        for (int o = 16; o > 0; o >>= 1)
            s += __shfl_xor_sync(0xffffffffu, s, o);
        const float inv = 1.f / s;
        sc[i * 68 + lane]      = e0 * inv;
        sc[i * 68 + lane + 32] = e1 * inv;
    }
    __syncthreads();

    // ---- convert P -> fp16 ----
    for (int i = tid; i < 64 * 32; i += 256) {        // 2048 half2s
        const int r = i >> 5, j2 = (i & 31) * 2;
        *(__half2*)&p16[r * 72 + j2] =
            __floats2half2_rn(sc[r * 68 + j2], sc[r * 68 + j2 + 1]);
    }
    __syncthreads();

    // ---- AV via HMMA: O(64x32) = p16 @ v16 -> Cf fp32 [64][36] ----
    {
        const int i0 = (wid >> 1) * 16;
        const int d0 = (wid & 1) * 16;
        wmma::fragment<wmma::accumulator, 16, 16, 16, float> fo;
        wmma::fill_fragment(fo, 0.0f);
#pragma unroll
        for (int kk = 0; kk < 64; kk += 16) {
            wmma::fragment<wmma::matrix_a, 16, 16, 16, __half, wmma::row_major> fa;
            wmma::fragment<wmma::matrix_b, 16, 16, 16, __half, wmma::row_major> fb;
            wmma::load_matrix_sync(fa, &p16[i0 * 72 + kk], 72);
            wmma::load_matrix_sync(fb, &v16[kk * 40 + d0], 40);
            wmma::mma_sync(fo, fa, fb, fo);
        }
        wmma::store_matrix_sync(&Cf[i0 * 36 + d0], fo, 36, wmma::mem_row_major);
    }
    __syncthreads();

    // ---- write fp16 attn output ----
    for (int i = tid; i < 64 * 16; i += 256) {        // 1024 half2s
        const int r = i >> 4, d2 = (i & 15) * 2;
        *(__half2*)&g_attn16[(g * 64 + r) * 256 + h * 32 + d2] =
            __floats2half2_rn(Cf[r * 36 + d2], Cf[r * 36 + d2 + 1]);
    }
}

// ---------------------------------------------------------------------------
// K3: out projection. 32x64 tiles, 256 blocks, full-K single-stage staging.
// smem: As half[32][264] (16896) + Bs half[64][264] (33792) = 50688 (dynamic).
// ---------------------------------------------------------------------------
static constexpr int K3_OFF_B = 16896;
static constexpr int K3_SMEM  = 50688;

__global__ void __launch_bounds__(256) out_hmma_kernel(
    const float* __restrict__ bo, float* __restrict__ outp)
{
    const int m0 = blockIdx.x * 32;       // 0..2016
    const int n0 = blockIdx.y * 64;       // 0..192
    const int tid = threadIdx.x;
    const int wid = tid >> 5;

    extern __shared__ __align__(32) char smem[];
    __half* As = (__half*)smem;                   // [32][264]
    __half* Bs = (__half*)(smem + K3_OFF_B);      // [64][264]

    {
        const __half* Ag = g_attn16 + m0 * 256;
        const __half* Bg = g_wT16 + (768 + n0) * 256;
#pragma unroll
        for (int t = 0; t < 4; t++) {
            const int idx = tid + t * 256;
            const int r = idx >> 5, q8 = (idx & 31) * 8;
            cp_async16(&As[r * 264 + q8], Ag + r * 256 + q8);
        }
#pragma unroll
        for (int t = 0; t < 8; t++) {
            const int idx = tid + t * 256;
            const int r = idx >> 5, q8 = (idx & 31) * 8;
            cp_async16(&Bs[r * 264 + q8], Bg + r * 256 + q8);
        }
        CP_COMMIT();
        CP_WAIT0();
    }
    __syncthreads();

    const int r0 = (wid & 1) * 16;
    const int c0 = (wid >> 1) * 16;
    wmma::fragment<wmma::accumulator, 16, 16, 16, float> fc;
    wmma::fill_fragment(fc, 0.0f);
#pragma unroll
    for (int kk = 0; kk < 256; kk += 16) {
        wmma::fragment<wmma::matrix_a, 16, 16, 16, __half, wmma::row_major> fa;
        wmma::fragment<wmma::matrix_b, 16, 16, 16, __half, wmma::col_major> fb;
        wmma::load_matrix_sync(fa, &As[r0 * 264 + kk], 264);
        wmma::load_matrix_sync(fb, &Bs[c0 * 264 + kk], 264);
        wmma::mma_sync(fc, fa, fb, fc);
    }
    __syncthreads();

    float* Cs = (float*)smem;                     // [32][68]
    wmma::store_matrix_sync(&Cs[r0 * 68 + c0], fc, 68, wmma::mem_row_major);
    __syncthreads();

#pragma unroll
    for (int i = tid; i < 512; i += 256) {
        const int r = i >> 4, c4 = (i & 15) * 4;
        float4 v = *(float4*)&Cs[r * 68 + c4];
        v.x += bo[n0 + c4 + 0];
        v.y += bo[n0 + c4 + 1];
        v.z += bo[n0 + c4 + 2];
        v.w += bo[n0 + c4 + 3];
        *(float4*)&outp[(m0 + r) * 256 + n0 + c4] = v;
    }
}

// ---------------------------------------------------------------------------
extern "C" void kernel_launch(void* const* d_in, const int* in_sizes, int n_in,
                              void* d_out, int out_size)
{
    const float* nodes     = (const float*)d_in[0];
    const float* edges     = (const float*)d_in[1];
    const int*   senders   = (const int*)d_in[3];
    const int*   receivers = (const int*)d_in[4];
    const float* Wq = (const float*)d_in[5];
    const float* bq = (const float*)d_in[6];
    const float* Wk = (const float*)d_in[7];
    const float* bk = (const float*)d_in[8];
    const float* Wv = (const float*)d_in[9];
    const float* bv = (const float*)d_in[10];
    const float* Wo = (const float*)d_in[11];
    const float* bo = (const float*)d_in[12];
    const float* We = (const float*)d_in[13];
    const float* be = (const float*)d_in[14];
    float* out = (float*)d_out;

    cudaFuncSetAttribute(fused_qkv_attn_kernel,
                         cudaFuncAttributeMaxDynamicSharedMemorySize, K2_SMEM);
    cudaFuncSetAttribute(out_hmma_kernel,
                         cudaFuncAttributeMaxDynamicSharedMemorySize, K3_SMEM);

    cvt_kernel<<<256, dim3(32, 8)>>>(Wq, Wk, Wv, Wo);
    fused_qkv_attn_kernel<<<GG * NH, 256, K2_SMEM>>>(nodes, senders, receivers,
                                                     edges, We, be, bq, bk, bv);
    out_hmma_kernel<<<dim3(64, 4), 256, K3_SMEM>>>(bo, out);
}